// round 10
// baseline (speedup 1.0000x reference)
#include <cuda_runtime.h>
#include <cuda_fp16.h>

#define C 64
#define MAX_N 50000
#define MAX_EN (800000 + MAX_N)
#define NPB 96              // nodes per block in k1
#define XR 68               // padded row stride (floats) for xs/wt

// ---------- scratch (device globals; no allocation allowed) ----------
__device__ __half g_h[(size_t)MAX_N * C];  // h = x @ W^T (fp16: node row = 1 L2 line)
__device__ float  g_si[MAX_N];
__device__ float  g_sj[MAX_N];
__device__ int    g_cnt[MAX_N];            // in-degree counts
__device__ int    g_offs[MAX_N + 1];       // CSR offsets
__device__ int    g_cur[MAX_N];            // scatter cursors (copy of offs)
__device__ uint2  g_edge[MAX_EN];          // packed (src, __float_as_uint(ex))

// ---------- K1: h = x W^T, s_i, s_j; zero g_cnt ----------
__global__ void k1_project(const float* __restrict__ x,
                           const float* __restrict__ emb,
                           const float* __restrict__ W,
                           const float* __restrict__ att_i,
                           const float* __restrict__ att_j,
                           const float* __restrict__ att_em_i,
                           const float* __restrict__ att_em_j,
                           int N)
{
    __shared__ float xs[NPB * XR];      // [local node][k]
    __shared__ float wt[C * XR];        // [k][c]  (W transposed)

    int t  = threadIdx.x;
    int nb = blockIdx.x * NPB;

    {   // zero counts (grid covers >= N threads)
        int z = blockIdx.x * 256 + t;
        if (z < N) g_cnt[z] = 0;
    }

    for (int idx = t; idx < C * C; idx += 256) {
        int c = idx >> 6, k = idx & 63;
        wt[k * XR + c] = W[idx];
    }
    for (int idx = t; idx < NPB * 16; idx += 256) {
        int node = idx >> 4, q = idx & 15;
        int n = nb + node;
        float4 v = (n < N) ? ((const float4*)x)[(size_t)n * 16 + q]
                           : make_float4(0.f, 0.f, 0.f, 0.f);
        *(float4*)&xs[node * XR + q * 4] = v;
    }
    __syncthreads();

    int c_slot = t & 15;
    int slot   = t >> 4;

    float acc[6][4];
#pragma unroll
    for (int i = 0; i < 6; i++)
#pragma unroll
        for (int j = 0; j < 4; j++) acc[i][j] = 0.f;

    const float* wp = &wt[c_slot * 4];
    const float* xp = &xs[slot * XR];

#pragma unroll 4
    for (int k = 0; k < C; k++) {
        float4 w4 = *(const float4*)&wp[k * XR];
#pragma unroll
        for (int i = 0; i < 6; i++) {
            float xk = xp[i * (16 * XR) + k];
            acc[i][0] = fmaf(xk, w4.x, acc[i][0]);
            acc[i][1] = fmaf(xk, w4.y, acc[i][1]);
            acc[i][2] = fmaf(xk, w4.z, acc[i][2]);
            acc[i][3] = fmaf(xk, w4.w, acc[i][3]);
        }
    }

    float4 ai  = ((const float4*)att_i)[c_slot];
    float4 aj  = ((const float4*)att_j)[c_slot];
    float4 aei = ((const float4*)att_em_i)[c_slot];
    float4 aej = ((const float4*)att_em_j)[c_slot];

#pragma unroll
    for (int i = 0; i < 6; i++) {
        int n = nb + slot + 16 * i;
        bool ok = (n < N);
        float4 a = make_float4(acc[i][0], acc[i][1], acc[i][2], acc[i][3]);
        float4 e = ok ? ((const float4*)emb)[(size_t)n * 16 + c_slot]
                      : make_float4(0.f, 0.f, 0.f, 0.f);
        if (ok) {
            __half2 h01 = __floats2half2_rn(a.x, a.y);
            __half2 h23 = __floats2half2_rn(a.z, a.w);
            uint2 pk;
            pk.x = *reinterpret_cast<unsigned*>(&h01);
            pk.y = *reinterpret_cast<unsigned*>(&h23);
            ((uint2*)g_h)[(size_t)n * 16 + c_slot] = pk;
        }

        float pi = a.x*ai.x + a.y*ai.y + a.z*ai.z + a.w*ai.w
                 + e.x*aei.x + e.y*aei.y + e.z*aei.z + e.w*aei.w;
        float pj = a.x*aj.x + a.y*aj.y + a.z*aj.z + a.w*aj.w
                 + e.x*aej.x + e.y*aej.y + e.z*aej.z + e.w*aej.w;
#pragma unroll
        for (int o = 8; o; o >>= 1) {
            pi += __shfl_xor_sync(0xffffffffu, pi, o);
            pj += __shfl_xor_sync(0xffffffffu, pj, o);
        }
        if (ok && c_slot == 0) { g_si[n] = pi; g_sj[n] = pj; }
    }
}

// ---------- K2a: in-degree count ----------
__global__ void k2_count(const int* __restrict__ ei, int E, int N)
{
    int e = blockIdx.x * blockDim.x + threadIdx.x;
    if (e >= E + N) return;
    int d = (e < E) ? __ldg(&ei[E + e]) : (e - E);
    atomicAdd(&g_cnt[d], 1);
}

// ---------- K2b: single-block exclusive scan of counts -> offs, cur ----------
__global__ void k2_scan(int N)
{
    __shared__ int sums[1024];
    int t = threadIdx.x;
    int chunk = (N + 1023) >> 10;
    int lo = t * chunk;
    int hi = min(lo + chunk, N);

    int s = 0;
    for (int i = lo; i < hi; i++) s += g_cnt[i];
    sums[t] = s;
    __syncthreads();

    // Hillis–Steele inclusive scan over 1024 partials
    for (int o = 1; o < 1024; o <<= 1) {
        int u = (t >= o) ? sums[t - o] : 0;
        __syncthreads();
        sums[t] += u;
        __syncthreads();
    }

    int run = sums[t] - s;                 // exclusive base for this chunk
    for (int i = lo; i < hi; i++) {
        int c = g_cnt[i];
        g_offs[i] = run;
        g_cur[i]  = run;
        run += c;
    }
    if (t == 1023) g_offs[N] = sums[1023];
}

// ---------- K2c: compute ex per edge, scatter (src, ex) into CSR buckets ----------
__global__ void k2_scatter(const int* __restrict__ ei, int E, int N)
{
    int e = blockIdx.x * blockDim.x + threadIdx.x;
    if (e >= E + N) return;
    int s, d;
    if (e < E) { s = __ldg(&ei[e]); d = __ldg(&ei[E + e]); }
    else       { s = d = e - E; }
    float a = g_si[d] + g_sj[s];
    a = (a > 0.f) ? a : 0.2f * a;          // leaky_relu, slope 0.2
    float ex = __expf(a);                   // softmax shift-invariance: no max pass
    int pos = atomicAdd(&g_cur[d], 1);
    g_edge[pos] = make_uint2((unsigned)s, __float_as_uint(ex));
}

// ---------- K3: per-node gather + normalize + bias + ReLU (16 lanes/node) ----------
__global__ void k3_gather(float* __restrict__ out, const float* __restrict__ bias,
                          int N)
{
    int t = threadIdx.x;
    int n = blockIdx.x * 16 + (t >> 4);
    int part = t & 15;
    if (n >= N) return;

    int i   = g_offs[n];
    int end = g_offs[n + 1];

    float4 acc = make_float4(0.f, 0.f, 0.f, 0.f);
    float den = 0.f;
    const uint2* hrow = (const uint2*)g_h;

    for (; i + 4 <= end; i += 4) {
        uint2 e0 = g_edge[i], e1 = g_edge[i + 1], e2 = g_edge[i + 2], e3 = g_edge[i + 3];
        uint2 p0 = hrow[(size_t)e0.x * 16 + part];
        uint2 p1 = hrow[(size_t)e1.x * 16 + part];
        uint2 p2 = hrow[(size_t)e2.x * 16 + part];
        uint2 p3 = hrow[(size_t)e3.x * 16 + part];
        float x0 = __uint_as_float(e0.y), x1 = __uint_as_float(e1.y);
        float x2 = __uint_as_float(e2.y), x3 = __uint_as_float(e3.y);
        den += (x0 + x1) + (x2 + x3);
        float2 a0 = __half22float2(*reinterpret_cast<__half2*>(&p0.x));
        float2 b0 = __half22float2(*reinterpret_cast<__half2*>(&p0.y));
        float2 a1 = __half22float2(*reinterpret_cast<__half2*>(&p1.x));
        float2 b1 = __half22float2(*reinterpret_cast<__half2*>(&p1.y));
        float2 a2 = __half22float2(*reinterpret_cast<__half2*>(&p2.x));
        float2 b2 = __half22float2(*reinterpret_cast<__half2*>(&p2.y));
        float2 a3 = __half22float2(*reinterpret_cast<__half2*>(&p3.x));
        float2 b3 = __half22float2(*reinterpret_cast<__half2*>(&p3.y));
        acc.x = fmaf(x0, a0.x, fmaf(x1, a1.x, fmaf(x2, a2.x, fmaf(x3, a3.x, acc.x))));
        acc.y = fmaf(x0, a0.y, fmaf(x1, a1.y, fmaf(x2, a2.y, fmaf(x3, a3.y, acc.y))));
        acc.z = fmaf(x0, b0.x, fmaf(x1, b1.x, fmaf(x2, b2.x, fmaf(x3, b3.x, acc.z))));
        acc.w = fmaf(x0, b0.y, fmaf(x1, b1.y, fmaf(x2, b2.y, fmaf(x3, b3.y, acc.w))));
    }
    for (; i < end; i++) {
        uint2 e0 = g_edge[i];
        uint2 p0 = hrow[(size_t)e0.x * 16 + part];
        float x0 = __uint_as_float(e0.y);
        den += x0;
        float2 a0 = __half22float2(*reinterpret_cast<__half2*>(&p0.x));
        float2 b0 = __half22float2(*reinterpret_cast<__half2*>(&p0.y));
        acc.x = fmaf(x0, a0.x, acc.x);
        acc.y = fmaf(x0, a0.y, acc.y);
        acc.z = fmaf(x0, b0.x, acc.z);
        acc.w = fmaf(x0, b0.y, acc.w);
    }

    float r = 1.f / (den + 1e-16f);
    float4 b = ((const float4*)bias)[part];
    float4 v;
    v.x = fmaxf(fmaf(acc.x, r, b.x), 0.f);
    v.y = fmaxf(fmaf(acc.y, r, b.y), 0.f);
    v.z = fmaxf(fmaf(acc.z, r, b.z), 0.f);
    v.w = fmaxf(fmaf(acc.w, r, b.w), 0.f);
    ((float4*)out)[(size_t)n * 16 + part] = v;
}

extern "C" void kernel_launch(void* const* d_in, const int* in_sizes, int n_in,
                              void* d_out, int out_size)
{
    const float* x        = (const float*)d_in[0];
    const int*   ei       = (const int*)  d_in[1];
    const float* emb      = (const float*)d_in[2];
    const float* W        = (const float*)d_in[3];
    const float* att_i    = (const float*)d_in[4];
    const float* att_j    = (const float*)d_in[5];
    const float* att_em_i = (const float*)d_in[6];
    const float* att_em_j = (const float*)d_in[7];
    const float* bias     = (const float*)d_in[8];
    float* out = (float*)d_out;

    int N  = in_sizes[0] / C;
    int E  = in_sizes[1] / 2;
    int EN = E + N;

    k1_project<<<(N + NPB - 1) / NPB, 256>>>(x, emb, W, att_i, att_j,
                                             att_em_i, att_em_j, N);
    k2_count<<<(EN + 255) / 256, 256>>>(ei, E, N);
    k2_scan<<<1, 1024>>>(N);
    k2_scatter<<<(EN + 255) / 256, 256>>>(ei, E, N);
    k3_gather<<<(N + 15) / 16, 256>>>(out, bias, N);
}